// round 14
// baseline (speedup 1.0000x reference)
#include <cuda_runtime.h>
#include <cuda_fp16.h>
#include <cstdint>

#define WINS   4096
#define NTOK   49
#define DIM    256
#define HEADS  8
#define DH     32
#define TTOT   (WINS * NTOK)      // 200704
#define QKV_E  768
#define SCALE  0.17677669529663687f
#define NCHUNK 4
#define GEMM_CTAS_PER_CHUNK (TTOT / 128 / NCHUNK)   // 392
#define ATTN_BLKS_PER_CHUNK (WINS * HEADS / NCHUNK) // 8192

// ------------------------- scratch (device globals) -------------------------
__device__ __half g_wq16[QKV_E * DIM];
__device__ __half g_wo16[DIM * DIM];
__device__ __half g_qkv [(size_t)TTOT * QKV_E];   // 308 MB
__device__ __half g_att [(size_t)TTOT * DIM];     // 103 MB
__device__ __half g_bias16[HEADS * 64 * 64];      // padded bias (fp16)

// ------------------------------ helpers ------------------------------------
__device__ __forceinline__ uint32_t smem_u32(const void* p) {
    uint32_t a;
    asm("{ .reg .u64 t; cvta.to.shared.u64 t, %1; cvt.u32.u64 %0, t; }"
        : "=r"(a) : "l"(p));
    return a;
}
__device__ __forceinline__ void cp16(uint32_t dst, const void* src) {
    asm volatile("cp.async.cg.shared.global [%0], [%1], 16;\n" :: "r"(dst), "l"(src));
}
__device__ __forceinline__ void cp_commit() {
    asm volatile("cp.async.commit_group;\n" ::);
}
template <int N> __device__ __forceinline__ void cp_wait() {
    asm volatile("cp.async.wait_group %0;\n" :: "n"(N) : "memory");
}
__device__ __forceinline__ void ldsm4(uint32_t& r0, uint32_t& r1, uint32_t& r2,
                                      uint32_t& r3, uint32_t a) {
    asm volatile("ldmatrix.sync.aligned.m8n8.x4.shared.b16 {%0,%1,%2,%3}, [%4];"
                 : "=r"(r0), "=r"(r1), "=r"(r2), "=r"(r3) : "r"(a) : "memory");
}
__device__ __forceinline__ void ldsm4t(uint32_t& r0, uint32_t& r1, uint32_t& r2,
                                       uint32_t& r3, uint32_t a) {
    asm volatile("ldmatrix.sync.aligned.m8n8.x4.trans.shared.b16 {%0,%1,%2,%3}, [%4];"
                 : "=r"(r0), "=r"(r1), "=r"(r2), "=r"(r3) : "r"(a) : "memory");
}
__device__ __forceinline__ void mma16816(float* d, uint32_t a0, uint32_t a1,
                                         uint32_t a2, uint32_t a3,
                                         uint32_t b0, uint32_t b1) {
    asm volatile(
        "mma.sync.aligned.m16n8k16.row.col.f32.f16.f16.f32 "
        "{%0,%1,%2,%3}, {%4,%5,%6,%7}, {%8,%9}, {%0,%1,%2,%3};"
        : "+f"(d[0]), "+f"(d[1]), "+f"(d[2]), "+f"(d[3])
        : "r"(a0), "r"(a1), "r"(a2), "r"(a3), "r"(b0), "r"(b1));
}
__device__ __forceinline__ uint32_t f22h2(float lo, float hi) {
    uint32_t r;
    asm("cvt.rn.f16x2.f32 %0, %1, %2;" : "=r"(r) : "f"(hi), "f"(lo));
    return r;
}

// ---------------------- GEMM (fp16 mma, A-resident) --------------------------
// R13 config + mbase chunk offset. 256 thr, 8 warps (2x4), warp tile 64x32,
// full A slab resident, B streamed via 4-stage cp.async, 1 barrier per K-step.
#define SAROW 528
#define SA_BYTES (128 * SAROW)
#define BGROW 80
#define BST  (128 * BGROW)
#define NSTG 4
#define GSMEM (SA_BYTES + NSTG * BST)   // 108544

template <int HALF_OUT, int A_FP32>
__global__ void __launch_bounds__(256, 2) gemm_h_kernel(
    const void* __restrict__ Av, const __half* __restrict__ B,
    void* __restrict__ Cv, int N, int mbase)
{
    extern __shared__ char smem[];
    const uint32_t sA = smem_u32(smem);
    const uint32_t sB = sA + SA_BYTES;

    const int tid = threadIdx.x, lane = tid & 31, wid = tid >> 5;
    const int wm = wid & 1, wn = wid >> 1;
    const int bm = (blockIdx.x + mbase) * 128;
    const int ntiles = N >> 7;
    const int NQ = ntiles * 8;

    const int b_row = tid >> 1;
    auto ld_B = [&](int q, int buf) {
        const int nt = q >> 3, ks = q & 7;
        const __half* src = B + (size_t)(nt * 128 + b_row) * DIM + ks * 32;
#pragma unroll
        for (int h = 0; h < 2; h++) {
            int ch = (tid & 1) + h * 2;
            cp16(sB + buf * BST + b_row * BGROW + ch * 16, src + ch * 8);
        }
        cp_commit();
    };

    if (A_FP32) {
        ld_B(0, 0);
        ld_B(1, 1);
        ld_B(2, 2);
        const float* Af = (const float*)Av;
#pragma unroll
        for (int it = 0; it < 16; it++) {
            int idx = tid + it * 256;
            int row = idx >> 5, ch = idx & 31;
            const float* src = Af + (size_t)(bm + row) * DIM + ch * 8;
            float4 v0 = *(const float4*)src;
            float4 v1 = *(const float4*)(src + 4);
            uint4 h = make_uint4(f22h2(v0.x, v0.y), f22h2(v0.z, v0.w),
                                 f22h2(v1.x, v1.y), f22h2(v1.z, v1.w));
            *(uint4*)(smem + row * SAROW + ch * 16) = h;
        }
    } else {
        const __half* Ah = (const __half*)Av;
#pragma unroll
        for (int it = 0; it < 16; it++) {
            int idx = tid + it * 256;
            int row = idx >> 5, ch = idx & 31;
            cp16(sA + row * SAROW + ch * 16,
                 Ah + (size_t)(bm + row) * DIM + ch * 8);
        }
        cp_commit();
        ld_B(0, 0);
        ld_B(1, 1);
        ld_B(2, 2);
    }

    const int l7 = lane & 7;
    const uint32_t aBase = sA + (wm * 64 + l7 + ((lane >> 3) & 1) * 8) * SAROW
                              + (lane >> 4) * 16;
    const uint32_t bBase = sB + (wn * 32 + (lane >> 4) * 8 + l7) * BGROW
                              + ((lane >> 3) & 1) * 16;

    const int r = lane >> 2, c = lane & 3;

    for (int nt = 0; nt < ntiles; nt++) {
        float acc[4][4][4];
#pragma unroll
        for (int mt = 0; mt < 4; mt++)
#pragma unroll
            for (int ntt = 0; ntt < 4; ntt++)
#pragma unroll
                for (int i = 0; i < 4; i++) acc[mt][ntt][i] = 0.f;

#pragma unroll
        for (int ks = 0; ks < 8; ks++) {
            const int q = nt * 8 + ks;
            const int rem = NQ - 1 - q;
            if (rem >= 2) cp_wait<2>(); else if (rem == 1) cp_wait<1>(); else cp_wait<0>();
            __syncthreads();
            const uint32_t bcur = bBase + (q & 3) * BST;

#pragma unroll
            for (int kt = 0; kt < 2; kt++) {
                uint32_t af[4][4], bf[4][2];
#pragma unroll
                for (int mt = 0; mt < 4; mt++)
                    ldsm4(af[mt][0], af[mt][1], af[mt][2], af[mt][3],
                          aBase + mt * 16 * SAROW + ks * 64 + kt * 32);
#pragma unroll
                for (int p = 0; p < 2; p++)
                    ldsm4(bf[2 * p][0], bf[2 * p][1], bf[2 * p + 1][0], bf[2 * p + 1][1],
                          bcur + p * 16 * BGROW + kt * 32);
#pragma unroll
                for (int mt = 0; mt < 4; mt++)
#pragma unroll
                    for (int ntt = 0; ntt < 4; ntt++)
                        mma16816(acc[mt][ntt], af[mt][0], af[mt][1], af[mt][2], af[mt][3],
                                 bf[ntt][0], bf[ntt][1]);
            }
            if (q + 3 < NQ) ld_B(q + 3, (q + 3) & 3);
        }

        const int bn = nt * 128;
#pragma unroll
        for (int mt = 0; mt < 4; mt++) {
            const int row = bm + wm * 64 + mt * 16 + r;
#pragma unroll
            for (int ntt = 0; ntt < 4; ntt++) {
                const int col = bn + wn * 32 + ntt * 8 + 2 * c;
                if (HALF_OUT) {
                    __half* C = (__half*)Cv;
                    *(uint32_t*)&C[(size_t)row * N + col] =
                        f22h2(acc[mt][ntt][0], acc[mt][ntt][1]);
                    *(uint32_t*)&C[(size_t)(row + 8) * N + col] =
                        f22h2(acc[mt][ntt][2], acc[mt][ntt][3]);
                } else {
                    float* C = (float*)Cv;
                    *(float2*)&C[(size_t)row * N + col] =
                        make_float2(acc[mt][ntt][0], acc[mt][ntt][1]);
                    *(float2*)&C[(size_t)(row + 8) * N + col] =
                        make_float2(acc[mt][ntt][2], acc[mt][ntt][3]);
                }
            }
        }
    }
}

// --------------------------- attention (fp16 mma) ---------------------------
#define AROW 40
#define BIASROW 72

__global__ void __launch_bounds__(128, 5) attn_kernel(
    const __half* __restrict__ qkv, const __half* __restrict__ bias16,
    __half* __restrict__ att, int blkbase)
{
    __shared__ __half q[64 * AROW];
    __shared__ __half k[64 * AROW];
    __shared__ __half v[64 * AROW];
    __shared__ __half bs[64 * BIASROW];

    const int tid  = threadIdx.x;
    const int lane = tid & 31;
    const int w    = tid >> 5;
    const int blk  = blockIdx.x + blkbase;
    const int win  = blk >> 3, head = blk & 7;

    // bias tile -> smem (coalesced)
    {
        const __half* bg = bias16 + head * 4096;
#pragma unroll
        for (int it = 0; it < 4; it++) {
            int i = tid + it * 128;
            int row = i >> 3, ch = i & 7;
            cp16(smem_u32(&bs[row * BIASROW + ch * 8]), bg + row * 64 + ch * 8);
        }
    }
    // zero pad rows 49..63
    {
        int rc = tid & 63;
        if (rc < 60) {
            int row = 49 + (rc >> 2), ch = rc & 3;
            __half* base = (tid < 64) ? q : k;
            *(uint4*)&base[row * AROW + ch * 8] = make_uint4(0, 0, 0, 0);
            if (tid < 64)
                *(uint4*)&v[row * AROW + ch * 8] = make_uint4(0, 0, 0, 0);
        }
    }
    // load q,k,v rows 0..48
    const __half* gbase = qkv + (size_t)win * NTOK * QKV_E + head * DH;
#pragma unroll
    for (int m = 0; m < 3; m++) {
        __half* base = (m == 0 ? q : (m == 1 ? k : v));
        const __half* gsrc = gbase + m * DIM;
#pragma unroll
        for (int it = 0; it < 2; it++) {
            int u = tid + it * 128;
            if (u < 196) {
                int row = u >> 2, ch = u & 3;
                cp16(smem_u32(&base[row * AROW + ch * 8]),
                     gsrc + (size_t)row * QKV_E + ch * 8);
            }
        }
    }
    cp_commit();
    cp_wait<0>();
    __syncthreads();

    const int l7 = lane & 7;
    const int wr = w * 16;
    const uint32_t qA = smem_u32(&q[(wr + l7 + ((lane >> 3) & 1) * 8) * AROW
                                    + (lane >> 4) * 8]);
    const uint32_t kB = smem_u32(&k[((lane >> 4) * 8 + l7) * AROW
                                    + ((lane >> 3) & 1) * 8]);
    const uint32_t vB = smem_u32(&v[(l7 + ((lane >> 3) & 1) * 8) * AROW
                                    + (lane >> 4) * 8]);

    float s[8][4];
#pragma unroll
    for (int nt = 0; nt < 8; nt++)
#pragma unroll
        for (int i = 0; i < 4; i++) s[nt][i] = 0.f;

#pragma unroll
    for (int kt = 0; kt < 2; kt++) {
        uint32_t a0, a1, a2, a3;
        ldsm4(a0, a1, a2, a3, qA + kt * 32);
#pragma unroll
        for (int p = 0; p < 4; p++) {
            uint32_t b0, b1, b2, b3;
            ldsm4(b0, b1, b2, b3, kB + p * 16 * AROW * 2 + kt * 32);
            mma16816(s[2 * p],     a0, a1, a2, a3, b0, b1);
            mma16816(s[2 * p + 1], a0, a1, a2, a3, b2, b3);
        }
    }

    const int r = lane >> 2, c = lane & 3;
    const __half* bp0 = &bs[(wr + r) * BIASROW + 2 * c];
    const __half* bp1 = &bs[(wr + r + 8) * BIASROW + 2 * c];
#pragma unroll
    for (int nt = 0; nt < 8; nt++) {
        uint32_t u0 = *(const uint32_t*)(bp0 + nt * 8);
        uint32_t u1 = *(const uint32_t*)(bp1 + nt * 8);
        float2 b0 = __half22float2(*(__half2*)&u0);
        float2 b1 = __half22float2(*(__half2*)&u1);
        s[nt][0] = fmaf(s[nt][0], SCALE, b0.x);
        s[nt][1] = fmaf(s[nt][1], SCALE, b0.y);
        s[nt][2] = fmaf(s[nt][2], SCALE, b1.x);
        s[nt][3] = fmaf(s[nt][3], SCALE, b1.y);
    }
    float m0 = -1e30f, m1 = -1e30f;
#pragma unroll
    for (int nt = 0; nt < 8; nt++) {
        m0 = fmaxf(m0, fmaxf(s[nt][0], s[nt][1]));
        m1 = fmaxf(m1, fmaxf(s[nt][2], s[nt][3]));
    }
    m0 = fmaxf(m0, __shfl_xor_sync(0xffffffffu, m0, 1));
    m0 = fmaxf(m0, __shfl_xor_sync(0xffffffffu, m0, 2));
    m1 = fmaxf(m1, __shfl_xor_sync(0xffffffffu, m1, 1));
    m1 = fmaxf(m1, __shfl_xor_sync(0xffffffffu, m1, 2));
    float sum0 = 0.f, sum1 = 0.f;
#pragma unroll
    for (int nt = 0; nt < 8; nt++) {
        s[nt][0] = __expf(s[nt][0] - m0);
        s[nt][1] = __expf(s[nt][1] - m0);
        s[nt][2] = __expf(s[nt][2] - m1);
        s[nt][3] = __expf(s[nt][3] - m1);
        sum0 += s[nt][0] + s[nt][1];
        sum1 += s[nt][2] + s[nt][3];
    }
    sum0 += __shfl_xor_sync(0xffffffffu, sum0, 1);
    sum0 += __shfl_xor_sync(0xffffffffu, sum0, 2);
    sum1 += __shfl_xor_sync(0xffffffffu, sum1, 1);
    sum1 += __shfl_xor_sync(0xffffffffu, sum1, 2);
    const float inv0 = 1.f / sum0, inv1 = 1.f / sum1;

    uint32_t pf[4][4];
#pragma unroll
    for (int kt = 0; kt < 4; kt++) {
        pf[kt][0] = f22h2(s[2 * kt][0],     s[2 * kt][1]);
        pf[kt][1] = f22h2(s[2 * kt][2],     s[2 * kt][3]);
        pf[kt][2] = f22h2(s[2 * kt + 1][0], s[2 * kt + 1][1]);
        pf[kt][3] = f22h2(s[2 * kt + 1][2], s[2 * kt + 1][3]);
    }

    float o[4][4];
#pragma unroll
    for (int nb = 0; nb < 4; nb++)
#pragma unroll
        for (int i = 0; i < 4; i++) o[nb][i] = 0.f;
#pragma unroll
    for (int kt = 0; kt < 4; kt++) {
#pragma unroll
        for (int p = 0; p < 2; p++) {
            uint32_t b0, b1, b2, b3;
            ldsm4t(b0, b1, b2, b3, vB + kt * 16 * AROW * 2 + p * 32);
            mma16816(o[2 * p],     pf[kt][0], pf[kt][1], pf[kt][2], pf[kt][3], b0, b1);
            mma16816(o[2 * p + 1], pf[kt][0], pf[kt][1], pf[kt][2], pf[kt][3], b2, b3);
        }
    }

    const int row0 = wr + r, row1 = wr + r + 8;
#pragma unroll
    for (int nb = 0; nb < 4; nb++) {
        const int col = head * DH + nb * 8 + 2 * c;
        if (row0 < NTOK)
            *(uint32_t*)&att[((size_t)win * NTOK + row0) * DIM + col] =
                f22h2(o[nb][0] * inv0, o[nb][1] * inv0);
        if (row1 < NTOK)
            *(uint32_t*)&att[((size_t)win * NTOK + row1) * DIM + col] =
                f22h2(o[nb][2] * inv1, o[nb][3] * inv1);
    }
}

// ------------------------------ prep kernel ---------------------------------
__global__ void prep_small_kernel(const float4* __restrict__ wq,
                                  const float4* __restrict__ wo,
                                  const float*  __restrict__ rel_emb,
                                  const int*    __restrict__ rel_idx,
                                  uint2* __restrict__ wq16,
                                  uint2* __restrict__ wo16,
                                  __half* __restrict__ bias16)
{
    const int NWQ = QKV_E * DIM / 4;
    const int NWO = DIM * DIM / 4;
    const int NB  = HEADS * 64 * 64;
    int i = blockIdx.x * 256 + threadIdx.x;
    if (i < NWQ) {
        float4 v = wq[i];
        wq16[i] = make_uint2(f22h2(v.x, v.y), f22h2(v.z, v.w));
    } else if (i < NWQ + NWO) {
        int j = i - NWQ;
        float4 v = wo[j];
        wo16[j] = make_uint2(f22h2(v.x, v.y), f22h2(v.z, v.w));
    } else if (i < NWQ + NWO + NB) {
        int e = i - NWQ - NWO;
        int h = e >> 12, rc = e & 4095, rr = rc >> 6, cc = rc & 63;
        float bv = (rr < NTOK && cc < NTOK)
                 ? rel_emb[rel_idx[rr * NTOK + cc] * HEADS + h] : -60000.f;
        bias16[e] = __float2half(bv);
    }
}

// ----------------------------------------------------------------------------
extern "C" void kernel_launch(void* const* d_in, const int* in_sizes, int n_in,
                              void* d_out, int out_size)
{
    const float* x       = (const float*)d_in[0];
    const float* w_qkv   = (const float*)d_in[1];
    const float* w_out   = (const float*)d_in[2];
    const float* rel_emb = (const float*)d_in[3];
    const int*   rel_idx = (const int*)d_in[4];
    float* out = (float*)d_out;

    __half *wq16, *wo16, *qkv, *att, *bias16;
    cudaGetSymbolAddress((void**)&wq16, g_wq16);
    cudaGetSymbolAddress((void**)&wo16, g_wo16);
    cudaGetSymbolAddress((void**)&qkv,  g_qkv);
    cudaGetSymbolAddress((void**)&att,  g_att);
    cudaGetSymbolAddress((void**)&bias16, g_bias16);

    cudaFuncSetAttribute((void*)gemm_h_kernel<1, 1>,
                         cudaFuncAttributeMaxDynamicSharedMemorySize, GSMEM);
    cudaFuncSetAttribute((void*)gemm_h_kernel<0, 0>,
                         cudaFuncAttributeMaxDynamicSharedMemorySize, GSMEM);

    // Side stream + events for chunked overlap (created at capture time only;
    // host-side objects, leaked deliberately — replay cost is zero).
    cudaStream_t s1;
    cudaStreamCreateWithFlags(&s1, cudaStreamNonBlocking);
    cudaEvent_t evQ[NCHUNK], evA[NCHUNK];
    for (int i = 0; i < NCHUNK; i++) {
        cudaEventCreateWithFlags(&evQ[i], cudaEventDisableTiming);
        cudaEventCreateWithFlags(&evA[i], cudaEventDisableTiming);
    }

    {
        int tot = QKV_E * DIM / 4 + DIM * DIM / 4 + HEADS * 64 * 64;
        prep_small_kernel<<<(tot + 255) / 256, 256>>>(
            (const float4*)w_qkv, (const float4*)w_out, rel_emb, rel_idx,
            (uint2*)wq16, (uint2*)wo16, bias16);
    }

    // qkv chunks on main stream; attn chunks on s1 as each qkv chunk lands
    for (int c = 0; c < NCHUNK; c++) {
        gemm_h_kernel<1, 1><<<GEMM_CTAS_PER_CHUNK, 256, GSMEM>>>(
            x, wq16, qkv, QKV_E, c * GEMM_CTAS_PER_CHUNK);
        cudaEventRecord(evQ[c], 0);
        cudaStreamWaitEvent(s1, evQ[c], 0);
        attn_kernel<<<ATTN_BLKS_PER_CHUNK, 128, 0, s1>>>(
            qkv, bias16, att, c * ATTN_BLKS_PER_CHUNK);
        cudaEventRecord(evA[c], s1);
    }
    // proj chunks on main stream, each gated on its attn chunk (joins s1)
    for (int c = 0; c < NCHUNK; c++) {
        cudaStreamWaitEvent(0, evA[c], 0);
        gemm_h_kernel<0, 0><<<GEMM_CTAS_PER_CHUNK, 256, GSMEM>>>(
            att, wo16, out, DIM, c * GEMM_CTAS_PER_CHUNK);
    }
}

// round 15
// speedup vs baseline: 1.1050x; 1.1050x over previous
#include <cuda_runtime.h>
#include <cuda_fp16.h>
#include <cstdint>

#define WINS   4096
#define NTOK   49
#define DIM    256
#define HEADS  8
#define DH     32
#define TTOT   (WINS * NTOK)      // 200704
#define QKV_E  768
#define SCALE  0.17677669529663687f

#define QKV_CHUNKS 2
#define QKV_CTAS   (TTOT / 128 / QKV_CHUNKS)    // 784
#define ACHUNKS    4
#define ATTN_BLKS  (WINS * HEADS / ACHUNKS)     // 8192
#define PROJ_CTAS  (TTOT / 128 / ACHUNKS)       // 392

// ------------------------- scratch (device globals) -------------------------
__device__ __half g_wq16[QKV_E * DIM];
__device__ __half g_wo16[DIM * DIM];
__device__ __half g_qkv [(size_t)TTOT * QKV_E];   // 308 MB
__device__ __half g_att [(size_t)TTOT * DIM];     // 103 MB
__device__ __half g_bias16[HEADS * 64 * 64];      // padded bias (fp16)

// ------------------------------ helpers ------------------------------------
__device__ __forceinline__ uint32_t smem_u32(const void* p) {
    uint32_t a;
    asm("{ .reg .u64 t; cvta.to.shared.u64 t, %1; cvt.u32.u64 %0, t; }"
        : "=r"(a) : "l"(p));
    return a;
}
__device__ __forceinline__ void cp16(uint32_t dst, const void* src) {
    asm volatile("cp.async.cg.shared.global [%0], [%1], 16;\n" :: "r"(dst), "l"(src));
}
__device__ __forceinline__ void cp_commit() {
    asm volatile("cp.async.commit_group;\n" ::);
}
template <int N> __device__ __forceinline__ void cp_wait() {
    asm volatile("cp.async.wait_group %0;\n" :: "n"(N) : "memory");
}
__device__ __forceinline__ void ldsm4(uint32_t& r0, uint32_t& r1, uint32_t& r2,
                                      uint32_t& r3, uint32_t a) {
    asm volatile("ldmatrix.sync.aligned.m8n8.x4.shared.b16 {%0,%1,%2,%3}, [%4];"
                 : "=r"(r0), "=r"(r1), "=r"(r2), "=r"(r3) : "r"(a) : "memory");
}
__device__ __forceinline__ void ldsm4t(uint32_t& r0, uint32_t& r1, uint32_t& r2,
                                       uint32_t& r3, uint32_t a) {
    asm volatile("ldmatrix.sync.aligned.m8n8.x4.trans.shared.b16 {%0,%1,%2,%3}, [%4];"
                 : "=r"(r0), "=r"(r1), "=r"(r2), "=r"(r3) : "r"(a) : "memory");
}
__device__ __forceinline__ void mma16816(float* d, uint32_t a0, uint32_t a1,
                                         uint32_t a2, uint32_t a3,
                                         uint32_t b0, uint32_t b1) {
    asm volatile(
        "mma.sync.aligned.m16n8k16.row.col.f32.f16.f16.f32 "
        "{%0,%1,%2,%3}, {%4,%5,%6,%7}, {%8,%9}, {%0,%1,%2,%3};"
        : "+f"(d[0]), "+f"(d[1]), "+f"(d[2]), "+f"(d[3])
        : "r"(a0), "r"(a1), "r"(a2), "r"(a3), "r"(b0), "r"(b1));
}
__device__ __forceinline__ uint32_t f22h2(float lo, float hi) {
    uint32_t r;
    asm("cvt.rn.f16x2.f32 %0, %1, %2;" : "=r"(r) : "f"(hi), "f"(lo));
    return r;
}

// ---------------------- GEMM (fp16 mma, A-resident) --------------------------
// 256 thr, 8 warps (2x4), warp tile 64x32, full A slab resident, B streamed
// via 3-stage cp.async (smem 96KB -> leaves room for an attn CTA per SM).
#define SAROW 528
#define SA_BYTES (128 * SAROW)
#define BGROW 80
#define BST  (128 * BGROW)
#define NSTG 3
#define GSMEM (SA_BYTES + NSTG * BST)   // 98304

template <int HALF_OUT, int A_FP32>
__global__ void __launch_bounds__(256, 2) gemm_h_kernel(
    const void* __restrict__ Av, const __half* __restrict__ B,
    void* __restrict__ Cv, int N, int mbase)
{
    extern __shared__ char smem[];
    const uint32_t sA = smem_u32(smem);
    const uint32_t sB = sA + SA_BYTES;

    const int tid = threadIdx.x, lane = tid & 31, wid = tid >> 5;
    const int wm = wid & 1, wn = wid >> 1;
    const int bm = (blockIdx.x + mbase) * 128;
    const int ntiles = N >> 7;
    const int NQ = ntiles * 8;

    const int b_row = tid >> 1;
    auto ld_B = [&](int q, int buf) {
        const int nt = q >> 3, ks = q & 7;
        const __half* src = B + (size_t)(nt * 128 + b_row) * DIM + ks * 32;
#pragma unroll
        for (int h = 0; h < 2; h++) {
            int ch = (tid & 1) + h * 2;
            cp16(sB + buf * BST + b_row * BGROW + ch * 16, src + ch * 8);
        }
        cp_commit();
    };

    if (A_FP32) {
        ld_B(0, 0);
        ld_B(1, 1);
        const float* Af = (const float*)Av;
#pragma unroll
        for (int it = 0; it < 16; it++) {
            int idx = tid + it * 256;
            int row = idx >> 5, ch = idx & 31;
            const float* src = Af + (size_t)(bm + row) * DIM + ch * 8;
            float4 v0 = *(const float4*)src;
            float4 v1 = *(const float4*)(src + 4);
            uint4 h = make_uint4(f22h2(v0.x, v0.y), f22h2(v0.z, v0.w),
                                 f22h2(v1.x, v1.y), f22h2(v1.z, v1.w));
            *(uint4*)(smem + row * SAROW + ch * 16) = h;
        }
    } else {
        const __half* Ah = (const __half*)Av;
#pragma unroll
        for (int it = 0; it < 16; it++) {
            int idx = tid + it * 256;
            int row = idx >> 5, ch = idx & 31;
            cp16(sA + row * SAROW + ch * 16,
                 Ah + (size_t)(bm + row) * DIM + ch * 8);
        }
        cp_commit();
        ld_B(0, 0);
        ld_B(1, 1);
    }

    const int l7 = lane & 7;
    const uint32_t aBase = sA + (wm * 64 + l7 + ((lane >> 3) & 1) * 8) * SAROW
                              + (lane >> 4) * 16;
    const uint32_t bBase = sB + (wn * 32 + (lane >> 4) * 8 + l7) * BGROW
                              + ((lane >> 3) & 1) * 16;

    const int r = lane >> 2, c = lane & 3;

    for (int nt = 0; nt < ntiles; nt++) {
        float acc[4][4][4];
#pragma unroll
        for (int mt = 0; mt < 4; mt++)
#pragma unroll
            for (int ntt = 0; ntt < 4; ntt++)
#pragma unroll
                for (int i = 0; i < 4; i++) acc[mt][ntt][i] = 0.f;

#pragma unroll
        for (int ks = 0; ks < 8; ks++) {
            const int q = nt * 8 + ks;
            const int rem = NQ - 1 - q;
            if (rem >= 1) cp_wait<1>(); else cp_wait<0>();
            __syncthreads();
            const uint32_t bcur = bBase + (q % NSTG) * BST;

#pragma unroll
            for (int kt = 0; kt < 2; kt++) {
                uint32_t af[4][4], bf[4][2];
#pragma unroll
                for (int mt = 0; mt < 4; mt++)
                    ldsm4(af[mt][0], af[mt][1], af[mt][2], af[mt][3],
                          aBase + mt * 16 * SAROW + ks * 64 + kt * 32);
#pragma unroll
                for (int p = 0; p < 2; p++)
                    ldsm4(bf[2 * p][0], bf[2 * p][1], bf[2 * p + 1][0], bf[2 * p + 1][1],
                          bcur + p * 16 * BGROW + kt * 32);
#pragma unroll
                for (int mt = 0; mt < 4; mt++)
#pragma unroll
                    for (int ntt = 0; ntt < 4; ntt++)
                        mma16816(acc[mt][ntt], af[mt][0], af[mt][1], af[mt][2], af[mt][3],
                                 bf[ntt][0], bf[ntt][1]);
            }
            if (q + 2 < NQ) ld_B(q + 2, (q + 2) % NSTG);
        }

        const int bn = nt * 128;
#pragma unroll
        for (int mt = 0; mt < 4; mt++) {
            const int row = bm + wm * 64 + mt * 16 + r;
#pragma unroll
            for (int ntt = 0; ntt < 4; ntt++) {
                const int col = bn + wn * 32 + ntt * 8 + 2 * c;
                if (HALF_OUT) {
                    __half* C = (__half*)Cv;
                    *(uint32_t*)&C[(size_t)row * N + col] =
                        f22h2(acc[mt][ntt][0], acc[mt][ntt][1]);
                    *(uint32_t*)&C[(size_t)(row + 8) * N + col] =
                        f22h2(acc[mt][ntt][2], acc[mt][ntt][3]);
                } else {
                    float* C = (float*)Cv;
                    *(float2*)&C[(size_t)row * N + col] =
                        make_float2(acc[mt][ntt][0], acc[mt][ntt][1]);
                    *(float2*)&C[(size_t)(row + 8) * N + col] =
                        make_float2(acc[mt][ntt][2], acc[mt][ntt][3]);
                }
            }
        }
    }
}

// --------------------------- attention (fp16 mma) ---------------------------
#define AROW 40
#define BIASROW 72

__global__ void __launch_bounds__(128, 5) attn_kernel(
    const __half* __restrict__ qkv, const __half* __restrict__ bias16,
    __half* __restrict__ att, int blkbase)
{
    __shared__ __half q[64 * AROW];
    __shared__ __half k[64 * AROW];
    __shared__ __half v[64 * AROW];
    __shared__ __half bs[64 * BIASROW];

    const int tid  = threadIdx.x;
    const int lane = tid & 31;
    const int w    = tid >> 5;
    const int blk  = blockIdx.x + blkbase;
    const int win  = blk >> 3, head = blk & 7;

    {
        const __half* bg = bias16 + head * 4096;
#pragma unroll
        for (int it = 0; it < 4; it++) {
            int i = tid + it * 128;
            int row = i >> 3, ch = i & 7;
            cp16(smem_u32(&bs[row * BIASROW + ch * 8]), bg + row * 64 + ch * 8);
        }
    }
    {
        int rc = tid & 63;
        if (rc < 60) {
            int row = 49 + (rc >> 2), ch = rc & 3;
            __half* base = (tid < 64) ? q : k;
            *(uint4*)&base[row * AROW + ch * 8] = make_uint4(0, 0, 0, 0);
            if (tid < 64)
                *(uint4*)&v[row * AROW + ch * 8] = make_uint4(0, 0, 0, 0);
        }
    }
    const __half* gbase = qkv + (size_t)win * NTOK * QKV_E + head * DH;
#pragma unroll
    for (int m = 0; m < 3; m++) {
        __half* base = (m == 0 ? q : (m == 1 ? k : v));
        const __half* gsrc = gbase + m * DIM;
#pragma unroll
        for (int it = 0; it < 2; it++) {
            int u = tid + it * 128;
            if (u < 196) {
                int row = u >> 2, ch = u & 3;
                cp16(smem_u32(&base[row * AROW + ch * 8]),
                     gsrc + (size_t)row * QKV_E + ch * 8);
            }
        }
    }
    cp_commit();
    cp_wait<0>();
    __syncthreads();

    const int l7 = lane & 7;
    const int wr = w * 16;
    const uint32_t qA = smem_u32(&q[(wr + l7 + ((lane >> 3) & 1) * 8) * AROW
                                    + (lane >> 4) * 8]);
    const uint32_t kB = smem_u32(&k[((lane >> 4) * 8 + l7) * AROW
                                    + ((lane >> 3) & 1) * 8]);
    const uint32_t vB = smem_u32(&v[(l7 + ((lane >> 3) & 1) * 8) * AROW
                                    + (lane >> 4) * 8]);

    float s[8][4];
#pragma unroll
    for (int nt = 0; nt < 8; nt++)
#pragma unroll
        for (int i = 0; i < 4; i++) s[nt][i] = 0.f;

#pragma unroll
    for (int kt = 0; kt < 2; kt++) {
        uint32_t a0, a1, a2, a3;
        ldsm4(a0, a1, a2, a3, qA + kt * 32);
#pragma unroll
        for (int p = 0; p < 4; p++) {
            uint32_t b0, b1, b2, b3;
            ldsm4(b0, b1, b2, b3, kB + p * 16 * AROW * 2 + kt * 32);
            mma16816(s[2 * p],     a0, a1, a2, a3, b0, b1);
            mma16816(s[2 * p + 1], a0, a1, a2, a3, b2, b3);
        }
    }

    const int r = lane >> 2, c = lane & 3;
    const __half* bp0 = &bs[(wr + r) * BIASROW + 2 * c];
    const __half* bp1 = &bs[(wr + r + 8) * BIASROW + 2 * c];
#pragma unroll
    for (int nt = 0; nt < 8; nt++) {
        uint32_t u0 = *(const uint32_t*)(bp0 + nt * 8);
        uint32_t u1 = *(const uint32_t*)(bp1 + nt * 8);
        float2 b0 = __half22float2(*(__half2*)&u0);
        float2 b1 = __half22float2(*(__half2*)&u1);
        s[nt][0] = fmaf(s[nt][0], SCALE, b0.x);
        s[nt][1] = fmaf(s[nt][1], SCALE, b0.y);
        s[nt][2] = fmaf(s[nt][2], SCALE, b1.x);
        s[nt][3] = fmaf(s[nt][3], SCALE, b1.y);
    }
    float m0 = -1e30f, m1 = -1e30f;
#pragma unroll
    for (int nt = 0; nt < 8; nt++) {
        m0 = fmaxf(m0, fmaxf(s[nt][0], s[nt][1]));
        m1 = fmaxf(m1, fmaxf(s[nt][2], s[nt][3]));
    }
    m0 = fmaxf(m0, __shfl_xor_sync(0xffffffffu, m0, 1));
    m0 = fmaxf(m0, __shfl_xor_sync(0xffffffffu, m0, 2));
    m1 = fmaxf(m1, __shfl_xor_sync(0xffffffffu, m1, 1));
    m1 = fmaxf(m1, __shfl_xor_sync(0xffffffffu, m1, 2));
    float sum0 = 0.f, sum1 = 0.f;
#pragma unroll
    for (int nt = 0; nt < 8; nt++) {
        s[nt][0] = __expf(s[nt][0] - m0);
        s[nt][1] = __expf(s[nt][1] - m0);
        s[nt][2] = __expf(s[nt][2] - m1);
        s[nt][3] = __expf(s[nt][3] - m1);
        sum0 += s[nt][0] + s[nt][1];
        sum1 += s[nt][2] + s[nt][3];
    }
    sum0 += __shfl_xor_sync(0xffffffffu, sum0, 1);
    sum0 += __shfl_xor_sync(0xffffffffu, sum0, 2);
    sum1 += __shfl_xor_sync(0xffffffffu, sum1, 1);
    sum1 += __shfl_xor_sync(0xffffffffu, sum1, 2);
    const float inv0 = 1.f / sum0, inv1 = 1.f / sum1;

    uint32_t pf[4][4];
#pragma unroll
    for (int kt = 0; kt < 4; kt++) {
        pf[kt][0] = f22h2(s[2 * kt][0],     s[2 * kt][1]);
        pf[kt][1] = f22h2(s[2 * kt][2],     s[2 * kt][3]);
        pf[kt][2] = f22h2(s[2 * kt + 1][0], s[2 * kt + 1][1]);
        pf[kt][3] = f22h2(s[2 * kt + 1][2], s[2 * kt + 1][3]);
    }

    float o[4][4];
#pragma unroll
    for (int nb = 0; nb < 4; nb++)
#pragma unroll
        for (int i = 0; i < 4; i++) o[nb][i] = 0.f;
#pragma unroll
    for (int kt = 0; kt < 4; kt++) {
#pragma unroll
        for (int p = 0; p < 2; p++) {
            uint32_t b0, b1, b2, b3;
            ldsm4t(b0, b1, b2, b3, vB + kt * 16 * AROW * 2 + p * 32);
            mma16816(o[2 * p],     pf[kt][0], pf[kt][1], pf[kt][2], pf[kt][3], b0, b1);
            mma16816(o[2 * p + 1], pf[kt][0], pf[kt][1], pf[kt][2], pf[kt][3], b2, b3);
        }
    }

    const int row0 = wr + r, row1 = wr + r + 8;
#pragma unroll
    for (int nb = 0; nb < 4; nb++) {
        const int col = head * DH + nb * 8 + 2 * c;
        if (row0 < NTOK)
            *(uint32_t*)&att[((size_t)win * NTOK + row0) * DIM + col] =
                f22h2(o[nb][0] * inv0, o[nb][1] * inv0);
        if (row1 < NTOK)
            *(uint32_t*)&att[((size_t)win * NTOK + row1) * DIM + col] =
                f22h2(o[nb][2] * inv1, o[nb][3] * inv1);
    }
}

// ------------------------------ prep kernel ---------------------------------
__global__ void prep_small_kernel(const float4* __restrict__ wq,
                                  const float4* __restrict__ wo,
                                  const float*  __restrict__ rel_emb,
                                  const int*    __restrict__ rel_idx,
                                  uint2* __restrict__ wq16,
                                  uint2* __restrict__ wo16,
                                  __half* __restrict__ bias16)
{
    const int NWQ = QKV_E * DIM / 4;
    const int NWO = DIM * DIM / 4;
    const int NB  = HEADS * 64 * 64;
    int i = blockIdx.x * 256 + threadIdx.x;
    if (i < NWQ) {
        float4 v = wq[i];
        wq16[i] = make_uint2(f22h2(v.x, v.y), f22h2(v.z, v.w));
    } else if (i < NWQ + NWO) {
        int j = i - NWQ;
        float4 v = wo[j];
        wo16[j] = make_uint2(f22h2(v.x, v.y), f22h2(v.z, v.w));
    } else if (i < NWQ + NWO + NB) {
        int e = i - NWQ - NWO;
        int h = e >> 12, rc = e & 4095, rr = rc >> 6, cc = rc & 63;
        float bv = (rr < NTOK && cc < NTOK)
                 ? rel_emb[rel_idx[rr * NTOK + cc] * HEADS + h] : -60000.f;
        bias16[e] = __float2half(bv);
    }
}

// ----------------------------------------------------------------------------
extern "C" void kernel_launch(void* const* d_in, const int* in_sizes, int n_in,
                              void* d_out, int out_size)
{
    const float* x       = (const float*)d_in[0];
    const float* w_qkv   = (const float*)d_in[1];
    const float* w_out   = (const float*)d_in[2];
    const float* rel_emb = (const float*)d_in[3];
    const int*   rel_idx = (const int*)d_in[4];
    float* out = (float*)d_out;

    __half *wq16, *wo16, *qkv, *att, *bias16;
    cudaGetSymbolAddress((void**)&wq16, g_wq16);
    cudaGetSymbolAddress((void**)&wo16, g_wo16);
    cudaGetSymbolAddress((void**)&qkv,  g_qkv);
    cudaGetSymbolAddress((void**)&att,  g_att);
    cudaGetSymbolAddress((void**)&bias16, g_bias16);

    cudaFuncSetAttribute((void*)gemm_h_kernel<1, 1>,
                         cudaFuncAttributeMaxDynamicSharedMemorySize, GSMEM);
    cudaFuncSetAttribute((void*)gemm_h_kernel<0, 0>,
                         cudaFuncAttributeMaxDynamicSharedMemorySize, GSMEM);

    cudaStream_t s1;
    cudaStreamCreateWithFlags(&s1, cudaStreamNonBlocking);
    cudaEvent_t evQ[QKV_CHUNKS], evA[ACHUNKS];
    for (int i = 0; i < QKV_CHUNKS; i++)
        cudaEventCreateWithFlags(&evQ[i], cudaEventDisableTiming);
    for (int i = 0; i < ACHUNKS; i++)
        cudaEventCreateWithFlags(&evA[i], cudaEventDisableTiming);

    {
        int tot = QKV_E * DIM / 4 + DIM * DIM / 4 + HEADS * 64 * 64;
        prep_small_kernel<<<(tot + 255) / 256, 256>>>(
            (const float4*)w_qkv, (const float4*)w_out, rel_emb, rel_idx,
            (uint2*)wq16, (uint2*)wo16, bias16);
    }

    // qkv in 2 halves; attn chunks (2 per half) ride along on s1 using the
    // spare smem slot per SM; proj chunks gated per attn chunk.
    for (int h = 0; h < QKV_CHUNKS; h++) {
        gemm_h_kernel<1, 1><<<QKV_CTAS, 256, GSMEM>>>(
            x, wq16, qkv, QKV_E, h * QKV_CTAS);
        cudaEventRecord(evQ[h], 0);
        cudaStreamWaitEvent(s1, evQ[h], 0);
        for (int c = h * 2; c < h * 2 + 2; c++) {
            attn_kernel<<<ATTN_BLKS, 128, 0, s1>>>(
                qkv, bias16, att, c * ATTN_BLKS);
            cudaEventRecord(evA[c], s1);
        }
    }
    for (int c = 0; c < ACHUNKS; c++) {
        cudaStreamWaitEvent(0, evA[c], 0);
        gemm_h_kernel<0, 0><<<PROJ_CTAS, 256, GSMEM>>>(
            att, wo16, out, DIM, c * PROJ_CTAS);
    }
}

// round 16
// speedup vs baseline: 1.1168x; 1.0107x over previous
#include <cuda_runtime.h>
#include <cuda_fp16.h>
#include <cstdint>

#define WINS   4096
#define NTOK   49
#define DIM    256
#define HEADS  8
#define DH     32
#define TTOT   (WINS * NTOK)      // 200704
#define QKV_E  768
#define SCALE  0.17677669529663687f

// ------------------------- scratch (device globals) -------------------------
__device__ __half g_wq16[QKV_E * DIM];
__device__ __half g_wo16[DIM * DIM];
__device__ __half g_qkv [(size_t)TTOT * QKV_E];   // 308 MB
__device__ __half g_att [(size_t)TTOT * DIM];     // 103 MB
__device__ __half g_bias16[HEADS * 64 * 64];      // padded bias (fp16)

// ------------------------------ helpers ------------------------------------
__device__ __forceinline__ uint32_t smem_u32(const void* p) {
    uint32_t a;
    asm("{ .reg .u64 t; cvta.to.shared.u64 t, %1; cvt.u32.u64 %0, t; }"
        : "=r"(a) : "l"(p));
    return a;
}
__device__ __forceinline__ void cp16(uint32_t dst, const void* src) {
    asm volatile("cp.async.cg.shared.global [%0], [%1], 16;\n" :: "r"(dst), "l"(src));
}
__device__ __forceinline__ void cp16ca(uint32_t dst, const void* src) {
    asm volatile("cp.async.ca.shared.global [%0], [%1], 16;\n" :: "r"(dst), "l"(src));
}
__device__ __forceinline__ void cp_commit() {
    asm volatile("cp.async.commit_group;\n" ::);
}
template <int N> __device__ __forceinline__ void cp_wait() {
    asm volatile("cp.async.wait_group %0;\n" :: "n"(N) : "memory");
}
__device__ __forceinline__ void ldsm4(uint32_t& r0, uint32_t& r1, uint32_t& r2,
                                      uint32_t& r3, uint32_t a) {
    asm volatile("ldmatrix.sync.aligned.m8n8.x4.shared.b16 {%0,%1,%2,%3}, [%4];"
                 : "=r"(r0), "=r"(r1), "=r"(r2), "=r"(r3) : "r"(a) : "memory");
}
__device__ __forceinline__ void ldsm4t(uint32_t& r0, uint32_t& r1, uint32_t& r2,
                                       uint32_t& r3, uint32_t a) {
    asm volatile("ldmatrix.sync.aligned.m8n8.x4.trans.shared.b16 {%0,%1,%2,%3}, [%4];"
                 : "=r"(r0), "=r"(r1), "=r"(r2), "=r"(r3) : "r"(a) : "memory");
}
__device__ __forceinline__ void mma16816(float* d, uint32_t a0, uint32_t a1,
                                         uint32_t a2, uint32_t a3,
                                         uint32_t b0, uint32_t b1) {
    asm volatile(
        "mma.sync.aligned.m16n8k16.row.col.f32.f16.f16.f32 "
        "{%0,%1,%2,%3}, {%4,%5,%6,%7}, {%8,%9}, {%0,%1,%2,%3};"
        : "+f"(d[0]), "+f"(d[1]), "+f"(d[2]), "+f"(d[3])
        : "r"(a0), "r"(a1), "r"(a2), "r"(a3), "r"(b0), "r"(b1));
}
__device__ __forceinline__ uint32_t f22h2(float lo, float hi) {
    uint32_t r;
    asm("cvt.rn.f16x2.f32 %0, %1, %2;" : "=r"(r) : "f"(hi), "f"(lo));
    return r;
}

// ---------------------- GEMM (fp16 mma, A-resident) --------------------------
// R13 config (best measured): 256 thr, 8 warps (2x4), warp tile 64x32, full A
// slab resident, B streamed via 4-stage cp.async, one barrier per K-step.
#define SAROW 528
#define SA_BYTES (128 * SAROW)
#define BGROW 80
#define BST  (128 * BGROW)
#define NSTG 4
#define GSMEM (SA_BYTES + NSTG * BST)   // 108544

template <int HALF_OUT, int A_FP32>
__global__ void __launch_bounds__(256, 2) gemm_h_kernel(
    const void* __restrict__ Av, const __half* __restrict__ B,
    void* __restrict__ Cv, int N)
{
    extern __shared__ char smem[];
    const uint32_t sA = smem_u32(smem);
    const uint32_t sB = sA + SA_BYTES;

    const int tid = threadIdx.x, lane = tid & 31, wid = tid >> 5;
    const int wm = wid & 1, wn = wid >> 1;
    const int bm = blockIdx.x * 128;
    const int ntiles = N >> 7;
    const int NQ = ntiles * 8;

    const int b_row = tid >> 1;
    auto ld_B = [&](int q, int buf) {
        const int nt = q >> 3, ks = q & 7;
        const __half* src = B + (size_t)(nt * 128 + b_row) * DIM + ks * 32;
#pragma unroll
        for (int h = 0; h < 2; h++) {
            int ch = (tid & 1) + h * 2;
            cp16(sB + buf * BST + b_row * BGROW + ch * 16, src + ch * 8);
        }
        cp_commit();
    };

    if (A_FP32) {
        ld_B(0, 0);
        ld_B(1, 1);
        ld_B(2, 2);
        const float* Af = (const float*)Av;
#pragma unroll
        for (int it = 0; it < 16; it++) {
            int idx = tid + it * 256;
            int row = idx >> 5, ch = idx & 31;
            const float* src = Af + (size_t)(bm + row) * DIM + ch * 8;
            float4 v0 = *(const float4*)src;
            float4 v1 = *(const float4*)(src + 4);
            uint4 h = make_uint4(f22h2(v0.x, v0.y), f22h2(v0.z, v0.w),
                                 f22h2(v1.x, v1.y), f22h2(v1.z, v1.w));
            *(uint4*)(smem + row * SAROW + ch * 16) = h;
        }
    } else {
        const __half* Ah = (const __half*)Av;
#pragma unroll
        for (int it = 0; it < 16; it++) {
            int idx = tid + it * 256;
            int row = idx >> 5, ch = idx & 31;
            cp16(sA + row * SAROW + ch * 16,
                 Ah + (size_t)(bm + row) * DIM + ch * 8);
        }
        cp_commit();
        ld_B(0, 0);
        ld_B(1, 1);
        ld_B(2, 2);
    }

    const int l7 = lane & 7;
    const uint32_t aBase = sA + (wm * 64 + l7 + ((lane >> 3) & 1) * 8) * SAROW
                              + (lane >> 4) * 16;
    const uint32_t bBase = sB + (wn * 32 + (lane >> 4) * 8 + l7) * BGROW
                              + ((lane >> 3) & 1) * 16;

    const int r = lane >> 2, c = lane & 3;

    for (int nt = 0; nt < ntiles; nt++) {
        float acc[4][4][4];
#pragma unroll
        for (int mt = 0; mt < 4; mt++)
#pragma unroll
            for (int ntt = 0; ntt < 4; ntt++)
#pragma unroll
                for (int i = 0; i < 4; i++) acc[mt][ntt][i] = 0.f;

#pragma unroll
        for (int ks = 0; ks < 8; ks++) {
            const int q = nt * 8 + ks;
            const int rem = NQ - 1 - q;
            if (rem >= 2) cp_wait<2>(); else if (rem == 1) cp_wait<1>(); else cp_wait<0>();
            __syncthreads();
            const uint32_t bcur = bBase + (q & 3) * BST;

#pragma unroll
            for (int kt = 0; kt < 2; kt++) {
                uint32_t af[4][4], bf[4][2];
#pragma unroll
                for (int mt = 0; mt < 4; mt++)
                    ldsm4(af[mt][0], af[mt][1], af[mt][2], af[mt][3],
                          aBase + mt * 16 * SAROW + ks * 64 + kt * 32);
#pragma unroll
                for (int p = 0; p < 2; p++)
                    ldsm4(bf[2 * p][0], bf[2 * p][1], bf[2 * p + 1][0], bf[2 * p + 1][1],
                          bcur + p * 16 * BGROW + kt * 32);
#pragma unroll
                for (int mt = 0; mt < 4; mt++)
#pragma unroll
                    for (int ntt = 0; ntt < 4; ntt++)
                        mma16816(acc[mt][ntt], af[mt][0], af[mt][1], af[mt][2], af[mt][3],
                                 bf[ntt][0], bf[ntt][1]);
            }
            if (q + 3 < NQ) ld_B(q + 3, (q + 3) & 3);
        }

        const int bn = nt * 128;
#pragma unroll
        for (int mt = 0; mt < 4; mt++) {
            const int row = bm + wm * 64 + mt * 16 + r;
#pragma unroll
            for (int ntt = 0; ntt < 4; ntt++) {
                const int col = bn + wn * 32 + ntt * 8 + 2 * c;
                if (HALF_OUT) {
                    __half* C = (__half*)Cv;
                    *(uint32_t*)&C[(size_t)row * N + col] =
                        f22h2(acc[mt][ntt][0], acc[mt][ntt][1]);
                    *(uint32_t*)&C[(size_t)(row + 8) * N + col] =
                        f22h2(acc[mt][ntt][2], acc[mt][ntt][3]);
                } else {
                    float* C = (float*)Cv;
                    *(float2*)&C[(size_t)row * N + col] =
                        make_float2(acc[mt][ntt][0], acc[mt][ntt][1]);
                    *(float2*)&C[(size_t)(row + 8) * N + col] =
                        make_float2(acc[mt][ntt][2], acc[mt][ntt][3]);
                }
            }
        }
    }
}

// --------------------------- attention (fp16 mma) ---------------------------
// Block = 2 windows x same head, 256 threads. Bias tile shared by both halves.
// Pad columns 56..63 (nt=7) skipped in softmax: bias -60000 => exp == 0,
// P fragments hard-zeroed => bit-identical result with ~12% fewer instrs.
#define AROW 40
#define BIASROW 72

__global__ void __launch_bounds__(256, 3) attn_kernel(
    const __half* __restrict__ qkv, const __half* __restrict__ bias16,
    __half* __restrict__ att)
{
    __shared__ __half q[2][64 * AROW];
    __shared__ __half k[2][64 * AROW];
    __shared__ __half v[2][64 * AROW];
    __shared__ __half bs[64 * BIASROW];

    const int tid  = threadIdx.x;
    const int lane = tid & 31;
    const int sub  = tid >> 7;          // which window half
    const int st   = tid & 127;
    const int w    = (tid >> 5) & 3;
    const int head = blockIdx.x & 7;
    const int win  = (blockIdx.x >> 3) * 2 + sub;

    __half* qs = q[sub]; __half* ks = k[sub]; __half* vs = v[sub];

    // bias tile -> smem once for both windows (512 chunks over 256 threads)
    {
        const __half* bg = bias16 + head * 4096;
#pragma unroll
        for (int it = 0; it < 2; it++) {
            int i = tid + it * 256;
            int row = i >> 3, ch = i & 7;
            cp16ca(smem_u32(&bs[row * BIASROW + ch * 8]), bg + row * 64 + ch * 8);
        }
    }
    // zero pad rows 49..63 of this sub's q,k,v
    {
        int rc = st & 63;
        if (rc < 60) {
            int row = 49 + (rc >> 2), ch = rc & 3;
            __half* base = (st < 64) ? qs : ks;
            *(uint4*)&base[row * AROW + ch * 8] = make_uint4(0, 0, 0, 0);
            if (st < 64)
                *(uint4*)&vs[row * AROW + ch * 8] = make_uint4(0, 0, 0, 0);
        }
    }
    // load q,k,v rows 0..48 of this sub's window
    const __half* gbase = qkv + (size_t)win * NTOK * QKV_E + head * DH;
#pragma unroll
    for (int m = 0; m < 3; m++) {
        __half* base = (m == 0 ? qs : (m == 1 ? ks : vs));
        const __half* gsrc = gbase + m * DIM;
#pragma unroll
        for (int it = 0; it < 2; it++) {
            int u = st + it * 128;
            if (u < 196) {
                int row = u >> 2, ch = u & 3;
                cp16(smem_u32(&base[row * AROW + ch * 8]),
                     gsrc + (size_t)row * QKV_E + ch * 8);
            }
        }
    }
    cp_commit();
    cp_wait<0>();
    __syncthreads();

    const int l7 = lane & 7;
    const int wr = w * 16;
    const uint32_t qA = smem_u32(&qs[(wr + l7 + ((lane >> 3) & 1) * 8) * AROW
                                     + (lane >> 4) * 8]);
    const uint32_t kB = smem_u32(&ks[((lane >> 4) * 8 + l7) * AROW
                                     + ((lane >> 3) & 1) * 8]);
    const uint32_t vB = smem_u32(&vs[(l7 + ((lane >> 3) & 1) * 8) * AROW
                                     + (lane >> 4) * 8]);

    float s[8][4];
#pragma unroll
    for (int nt = 0; nt < 8; nt++)
#pragma unroll
        for (int i = 0; i < 4; i++) s[nt][i] = 0.f;

#pragma unroll
    for (int kt = 0; kt < 2; kt++) {
        uint32_t a0, a1, a2, a3;
        ldsm4(a0, a1, a2, a3, qA + kt * 32);
#pragma unroll
        for (int p = 0; p < 4; p++) {
            uint32_t b0, b1, b2, b3;
            ldsm4(b0, b1, b2, b3, kB + p * 16 * AROW * 2 + kt * 32);
            mma16816(s[2 * p],     a0, a1, a2, a3, b0, b1);
            mma16816(s[2 * p + 1], a0, a1, a2, a3, b2, b3);
        }
    }

    // softmax over cols 0..55 only (nt<7); cols 56..63 are pad (exp == 0)
    const int r = lane >> 2, c = lane & 3;
    const __half* bp0 = &bs[(wr + r) * BIASROW + 2 * c];
    const __half* bp1 = &bs[(wr + r + 8) * BIASROW + 2 * c];
#pragma unroll
    for (int nt = 0; nt < 7; nt++) {
        uint32_t u0 = *(const uint32_t*)(bp0 + nt * 8);
        uint32_t u1 = *(const uint32_t*)(bp1 + nt * 8);
        float2 b0 = __half22float2(*(__half2*)&u0);
        float2 b1 = __half22float2(*(__half2*)&u1);
        s[nt][0] = fmaf(s[nt][0], SCALE, b0.x);
        s[nt][1] = fmaf(s[nt][1], SCALE, b0.y);
        s[nt][2] = fmaf(s[nt][2], SCALE, b1.x);
        s[nt][3] = fmaf(s[nt][3], SCALE, b1.y);
    }
    float m0 = -1e30f, m1 = -1e30f;
#pragma unroll
    for (int nt = 0; nt < 7; nt++) {
        m0 = fmaxf(m0, fmaxf(s[nt][0], s[nt][1]));
        m1 = fmaxf(m1, fmaxf(s[nt][2], s[nt][3]));
    }
    m0 = fmaxf(m0, __shfl_xor_sync(0xffffffffu, m0, 1));
    m0 = fmaxf(m0, __shfl_xor_sync(0xffffffffu, m0, 2));
    m1 = fmaxf(m1, __shfl_xor_sync(0xffffffffu, m1, 1));
    m1 = fmaxf(m1, __shfl_xor_sync(0xffffffffu, m1, 2));
    float sum0 = 0.f, sum1 = 0.f;
#pragma unroll
    for (int nt = 0; nt < 7; nt++) {
        s[nt][0] = __expf(s[nt][0] - m0);
        s[nt][1] = __expf(s[nt][1] - m0);
        s[nt][2] = __expf(s[nt][2] - m1);
        s[nt][3] = __expf(s[nt][3] - m1);
        sum0 += s[nt][0] + s[nt][1];
        sum1 += s[nt][2] + s[nt][3];
    }
    sum0 += __shfl_xor_sync(0xffffffffu, sum0, 1);
    sum0 += __shfl_xor_sync(0xffffffffu, sum0, 2);
    sum1 += __shfl_xor_sync(0xffffffffu, sum1, 1);
    sum1 += __shfl_xor_sync(0xffffffffu, sum1, 2);
    const float inv0 = 1.f / sum0, inv1 = 1.f / sum1;

    uint32_t pf[4][4];
#pragma unroll
    for (int kt = 0; kt < 3; kt++) {
        pf[kt][0] = f22h2(s[2 * kt][0],     s[2 * kt][1]);
        pf[kt][1] = f22h2(s[2 * kt][2],     s[2 * kt][3]);
        pf[kt][2] = f22h2(s[2 * kt + 1][0], s[2 * kt + 1][1]);
        pf[kt][3] = f22h2(s[2 * kt + 1][2], s[2 * kt + 1][3]);
    }
    pf[3][0] = f22h2(s[6][0], s[6][1]);   // cols 48..55 (real col 48)
    pf[3][1] = f22h2(s[6][2], s[6][3]);
    pf[3][2] = 0u;                        // cols 56..63: pure pad -> P = 0
    pf[3][3] = 0u;

    float o[4][4];
#pragma unroll
    for (int nb = 0; nb < 4; nb++)
#pragma unroll
        for (int i = 0; i < 4; i++) o[nb][i] = 0.f;
#pragma unroll
    for (int kt = 0; kt < 4; kt++) {
#pragma unroll
        for (int p = 0; p < 2; p++) {
            uint32_t b0, b1, b2, b3;
            ldsm4t(b0, b1, b2, b3, vB + kt * 16 * AROW * 2 + p * 32);
            mma16816(o[2 * p],     pf[kt][0], pf[kt][1], pf[kt][2], pf[kt][3], b0, b1);
            mma16816(o[2 * p + 1], pf[kt][0], pf[kt][1], pf[kt][2], pf[kt][3], b2, b3);
        }
    }

    const int row0 = wr + r, row1 = wr + r + 8;
#pragma unroll
    for (int nb = 0; nb < 4; nb++) {
        const int col = head * DH + nb * 8 + 2 * c;
        if (row0 < NTOK)
            *(uint32_t*)&att[((size_t)win * NTOK + row0) * DIM + col] =
                f22h2(o[nb][0] * inv0, o[nb][1] * inv0);
        if (row1 < NTOK)
            *(uint32_t*)&att[((size_t)win * NTOK + row1) * DIM + col] =
                f22h2(o[nb][2] * inv1, o[nb][3] * inv1);
    }
}

// ------------------------------ prep kernel ---------------------------------
__global__ void prep_small_kernel(const float4* __restrict__ wq,
                                  const float4* __restrict__ wo,
                                  const float*  __restrict__ rel_emb,
                                  const int*    __restrict__ rel_idx,
                                  uint2* __restrict__ wq16,
                                  uint2* __restrict__ wo16,
                                  __half* __restrict__ bias16)
{
    const int NWQ = QKV_E * DIM / 4;
    const int NWO = DIM * DIM / 4;
    const int NB  = HEADS * 64 * 64;
    int i = blockIdx.x * 256 + threadIdx.x;
    if (i < NWQ) {
        float4 v = wq[i];
        wq16[i] = make_uint2(f22h2(v.x, v.y), f22h2(v.z, v.w));
    } else if (i < NWQ + NWO) {
        int j = i - NWQ;
        float4 v = wo[j];
        wo16[j] = make_uint2(f22h2(v.x, v.y), f22h2(v.z, v.w));
    } else if (i < NWQ + NWO + NB) {
        int e = i - NWQ - NWO;
        int h = e >> 12, rc = e & 4095, rr = rc >> 6, cc = rc & 63;
        float bv = (rr < NTOK && cc < NTOK)
                 ? rel_emb[rel_idx[rr * NTOK + cc] * HEADS + h] : -60000.f;
        bias16[e] = __float2half(bv);
    }
}

// ----------------------------------------------------------------------------
extern "C" void kernel_launch(void* const* d_in, const int* in_sizes, int n_in,
                              void* d_out, int out_size)
{
    const float* x       = (const float*)d_in[0];
    const float* w_qkv   = (const float*)d_in[1];
    const float* w_out   = (const float*)d_in[2];
    const float* rel_emb = (const float*)d_in[3];
    const int*   rel_idx = (const int*)d_in[4];
    float* out = (float*)d_out;

    __half *wq16, *wo16, *qkv, *att, *bias16;
    cudaGetSymbolAddress((void**)&wq16, g_wq16);
    cudaGetSymbolAddress((void**)&wo16, g_wo16);
    cudaGetSymbolAddress((void**)&qkv,  g_qkv);
    cudaGetSymbolAddress((void**)&att,  g_att);
    cudaGetSymbolAddress((void**)&bias16, g_bias16);

    cudaFuncSetAttribute((void*)gemm_h_kernel<1, 1>,
                         cudaFuncAttributeMaxDynamicSharedMemorySize, GSMEM);
    cudaFuncSetAttribute((void*)gemm_h_kernel<0, 0>,
                         cudaFuncAttributeMaxDynamicSharedMemorySize, GSMEM);

    {
        int tot = QKV_E * DIM / 4 + DIM * DIM / 4 + HEADS * 64 * 64;
        prep_small_kernel<<<(tot + 255) / 256, 256>>>(
            (const float4*)w_qkv, (const float4*)w_out, rel_emb, rel_idx,
            (uint2*)wq16, (uint2*)wo16, bias16);
    }

    // 1) qkv = x @ w_qkv^T   (A fp32->fp16 conversion fused into slab load)
    gemm_h_kernel<1, 1><<<TTOT / 128, 256, GSMEM>>>(x, wq16, qkv, QKV_E);

    // 2) windowed attention (2 windows per block)
    attn_kernel<<<WINS * HEADS / 2, 256>>>(qkv, bias16, att);

    // 3) out = att @ w_out^T
    gemm_h_kernel<0, 0><<<TTOT / 128, 256, GSMEM>>>(att, wo16, out, DIM);
}

// round 17
// speedup vs baseline: 1.1559x; 1.0350x over previous
#include <cuda_runtime.h>
#include <cuda_fp16.h>
#include <cstdint>

#define WINS   4096
#define NTOK   49
#define DIM    256
#define HEADS  8
#define DH     32
#define TTOT   (WINS * NTOK)      // 200704
#define QKV_E  768
#define SCALE  0.17677669529663687f

// ------------------------- scratch (device globals) -------------------------
__device__ __half g_wq16[QKV_E * DIM];
__device__ __half g_wo16[DIM * DIM];
__device__ __half g_qkv [(size_t)TTOT * QKV_E];   // 308 MB
__device__ __half g_att [(size_t)TTOT * DIM];     // 103 MB
__device__ __half g_bias16[HEADS * 64 * 64];      // padded bias (fp16)

// ------------------------------ helpers ------------------------------------
__device__ __forceinline__ uint32_t smem_u32(const void* p) {
    uint32_t a;
    asm("{ .reg .u64 t; cvta.to.shared.u64 t, %1; cvt.u32.u64 %0, t; }"
        : "=r"(a) : "l"(p));
    return a;
}
__device__ __forceinline__ void cp16(uint32_t dst, const void* src) {
    asm volatile("cp.async.cg.shared.global [%0], [%1], 16;\n" :: "r"(dst), "l"(src));
}
__device__ __forceinline__ void cp_commit() {
    asm volatile("cp.async.commit_group;\n" ::);
}
template <int N> __device__ __forceinline__ void cp_wait() {
    asm volatile("cp.async.wait_group %0;\n" :: "n"(N) : "memory");
}
__device__ __forceinline__ void ldsm4(uint32_t& r0, uint32_t& r1, uint32_t& r2,
                                      uint32_t& r3, uint32_t a) {
    asm volatile("ldmatrix.sync.aligned.m8n8.x4.shared.b16 {%0,%1,%2,%3}, [%4];"
                 : "=r"(r0), "=r"(r1), "=r"(r2), "=r"(r3) : "r"(a) : "memory");
}
__device__ __forceinline__ void ldsm4t(uint32_t& r0, uint32_t& r1, uint32_t& r2,
                                       uint32_t& r3, uint32_t a) {
    asm volatile("ldmatrix.sync.aligned.m8n8.x4.trans.shared.b16 {%0,%1,%2,%3}, [%4];"
                 : "=r"(r0), "=r"(r1), "=r"(r2), "=r"(r3) : "r"(a) : "memory");
}
__device__ __forceinline__ void mma16816(float* d, uint32_t a0, uint32_t a1,
                                         uint32_t a2, uint32_t a3,
                                         uint32_t b0, uint32_t b1) {
    asm volatile(
        "mma.sync.aligned.m16n8k16.row.col.f32.f16.f16.f32 "
        "{%0,%1,%2,%3}, {%4,%5,%6,%7}, {%8,%9}, {%0,%1,%2,%3};"
        : "+f"(d[0]), "+f"(d[1]), "+f"(d[2]), "+f"(d[3])
        : "r"(a0), "r"(a1), "r"(a2), "r"(a3), "r"(b0), "r"(b1));
}
__device__ __forceinline__ uint32_t f22h2(float lo, float hi) {
    uint32_t r;
    asm("cvt.rn.f16x2.f32 %0, %1, %2;" : "=r"(r) : "f"(hi), "f"(lo));
    return r;
}

// ---------------------- GEMM (fp16 mma, A-resident) --------------------------
// R13 config (best measured): 256 thr, 8 warps (2x4), warp tile 64x32, full A
// slab resident, B streamed via 4-stage cp.async, one barrier per K-step.
#define SAROW 528
#define SA_BYTES (128 * SAROW)
#define BGROW 80
#define BST  (128 * BGROW)
#define NSTG 4
#define GSMEM (SA_BYTES + NSTG * BST)   // 108544

template <int HALF_OUT, int A_FP32>
__global__ void __launch_bounds__(256, 2) gemm_h_kernel(
    const void* __restrict__ Av, const __half* __restrict__ B,
    void* __restrict__ Cv, int N)
{
    extern __shared__ char smem[];
    const uint32_t sA = smem_u32(smem);
    const uint32_t sB = sA + SA_BYTES;

    const int tid = threadIdx.x, lane = tid & 31, wid = tid >> 5;
    const int wm = wid & 1, wn = wid >> 1;
    const int bm = blockIdx.x * 128;
    const int ntiles = N >> 7;
    const int NQ = ntiles * 8;

    const int b_row = tid >> 1;
    auto ld_B = [&](int q, int buf) {
        const int nt = q >> 3, ks = q & 7;
        const __half* src = B + (size_t)(nt * 128 + b_row) * DIM + ks * 32;
#pragma unroll
        for (int h = 0; h < 2; h++) {
            int ch = (tid & 1) + h * 2;
            cp16(sB + buf * BST + b_row * BGROW + ch * 16, src + ch * 8);
        }
        cp_commit();
    };

    if (A_FP32) {
        ld_B(0, 0);
        ld_B(1, 1);
        ld_B(2, 2);
        const float* Af = (const float*)Av;
#pragma unroll
        for (int it = 0; it < 16; it++) {
            int idx = tid + it * 256;
            int row = idx >> 5, ch = idx & 31;
            const float* src = Af + (size_t)(bm + row) * DIM + ch * 8;
            float4 v0 = *(const float4*)src;
            float4 v1 = *(const float4*)(src + 4);
            uint4 h = make_uint4(f22h2(v0.x, v0.y), f22h2(v0.z, v0.w),
                                 f22h2(v1.x, v1.y), f22h2(v1.z, v1.w));
            *(uint4*)(smem + row * SAROW + ch * 16) = h;
        }
    } else {
        const __half* Ah = (const __half*)Av;
#pragma unroll
        for (int it = 0; it < 16; it++) {
            int idx = tid + it * 256;
            int row = idx >> 5, ch = idx & 31;
            cp16(sA + row * SAROW + ch * 16,
                 Ah + (size_t)(bm + row) * DIM + ch * 8);
        }
        cp_commit();
        ld_B(0, 0);
        ld_B(1, 1);
        ld_B(2, 2);
    }

    const int l7 = lane & 7;
    const uint32_t aBase = sA + (wm * 64 + l7 + ((lane >> 3) & 1) * 8) * SAROW
                              + (lane >> 4) * 16;
    const uint32_t bBase = sB + (wn * 32 + (lane >> 4) * 8 + l7) * BGROW
                              + ((lane >> 3) & 1) * 16;

    const int r = lane >> 2, c = lane & 3;

    for (int nt = 0; nt < ntiles; nt++) {
        float acc[4][4][4];
#pragma unroll
        for (int mt = 0; mt < 4; mt++)
#pragma unroll
            for (int ntt = 0; ntt < 4; ntt++)
#pragma unroll
                for (int i = 0; i < 4; i++) acc[mt][ntt][i] = 0.f;

#pragma unroll
        for (int ks = 0; ks < 8; ks++) {
            const int q = nt * 8 + ks;
            const int rem = NQ - 1 - q;
            if (rem >= 2) cp_wait<2>(); else if (rem == 1) cp_wait<1>(); else cp_wait<0>();
            __syncthreads();
            const uint32_t bcur = bBase + (q & 3) * BST;

#pragma unroll
            for (int kt = 0; kt < 2; kt++) {
                uint32_t af[4][4], bf[4][2];
#pragma unroll
                for (int mt = 0; mt < 4; mt++)
                    ldsm4(af[mt][0], af[mt][1], af[mt][2], af[mt][3],
                          aBase + mt * 16 * SAROW + ks * 64 + kt * 32);
#pragma unroll
                for (int p = 0; p < 2; p++)
                    ldsm4(bf[2 * p][0], bf[2 * p][1], bf[2 * p + 1][0], bf[2 * p + 1][1],
                          bcur + p * 16 * BGROW + kt * 32);
#pragma unroll
                for (int mt = 0; mt < 4; mt++)
#pragma unroll
                    for (int ntt = 0; ntt < 4; ntt++)
                        mma16816(acc[mt][ntt], af[mt][0], af[mt][1], af[mt][2], af[mt][3],
                                 bf[ntt][0], bf[ntt][1]);
            }
            if (q + 3 < NQ) ld_B(q + 3, (q + 3) & 3);
        }

        const int bn = nt * 128;
#pragma unroll
        for (int mt = 0; mt < 4; mt++) {
            const int row = bm + wm * 64 + mt * 16 + r;
#pragma unroll
            for (int ntt = 0; ntt < 4; ntt++) {
                const int col = bn + wn * 32 + ntt * 8 + 2 * c;
                if (HALF_OUT) {
                    __half* C = (__half*)Cv;
                    *(uint32_t*)&C[(size_t)row * N + col] =
                        f22h2(acc[mt][ntt][0], acc[mt][ntt][1]);
                    *(uint32_t*)&C[(size_t)(row + 8) * N + col] =
                        f22h2(acc[mt][ntt][2], acc[mt][ntt][3]);
                } else {
                    float* C = (float*)Cv;
                    *(float2*)&C[(size_t)row * N + col] =
                        make_float2(acc[mt][ntt][0], acc[mt][ntt][1]);
                    *(float2*)&C[(size_t)(row + 8) * N + col] =
                        make_float2(acc[mt][ntt][2], acc[mt][ntt][3]);
                }
            }
        }
    }
}

// --------------------------- attention (fp16 mma) ---------------------------
// R13 structure (1 window-head per 128-thread block), plus:
//  - occupancy 6 CTAs/SM (73 regs < 85 budget)
//  - pad-column skip: cols 56..63 (nt=7) excluded from softmax (exp == 0),
//    P fragments hard-zeroed -> bit-identical result, fewer instructions.
#define AROW 40
#define BIASROW 72

__global__ void __launch_bounds__(128, 6) attn_kernel(
    const __half* __restrict__ qkv, const __half* __restrict__ bias16,
    __half* __restrict__ att)
{
    __shared__ __half q[64 * AROW];
    __shared__ __half k[64 * AROW];
    __shared__ __half v[64 * AROW];
    __shared__ __half bs[64 * BIASROW];

    const int tid  = threadIdx.x;
    const int lane = tid & 31;
    const int w    = tid >> 5;
    const int win  = blockIdx.x >> 3, head = blockIdx.x & 7;

    // bias tile -> smem (coalesced)
    {
        const __half* bg = bias16 + head * 4096;
#pragma unroll
        for (int it = 0; it < 4; it++) {
            int i = tid + it * 128;
            int row = i >> 3, ch = i & 7;
            cp16(smem_u32(&bs[row * BIASROW + ch * 8]), bg + row * 64 + ch * 8);
        }
    }
    // zero pad rows 49..63
    {
        int rc = tid & 63;
        if (rc < 60) {
            int row = 49 + (rc >> 2), ch = rc & 3;
            __half* base = (tid < 64) ? q : k;
            *(uint4*)&base[row * AROW + ch * 8] = make_uint4(0, 0, 0, 0);
            if (tid < 64)
                *(uint4*)&v[row * AROW + ch * 8] = make_uint4(0, 0, 0, 0);
        }
    }
    // load q,k,v rows 0..48
    const __half* gbase = qkv + (size_t)win * NTOK * QKV_E + head * DH;
#pragma unroll
    for (int m = 0; m < 3; m++) {
        __half* base = (m == 0 ? q : (m == 1 ? k : v));
        const __half* gsrc = gbase + m * DIM;
#pragma unroll
        for (int it = 0; it < 2; it++) {
            int u = tid + it * 128;
            if (u < 196) {
                int row = u >> 2, ch = u & 3;
                cp16(smem_u32(&base[row * AROW + ch * 8]),
                     gsrc + (size_t)row * QKV_E + ch * 8);
            }
        }
    }
    cp_commit();
    cp_wait<0>();
    __syncthreads();

    const int l7 = lane & 7;
    const int wr = w * 16;
    const uint32_t qA = smem_u32(&q[(wr + l7 + ((lane >> 3) & 1) * 8) * AROW
                                    + (lane >> 4) * 8]);
    const uint32_t kB = smem_u32(&k[((lane >> 4) * 8 + l7) * AROW
                                    + ((lane >> 3) & 1) * 8]);
    const uint32_t vB = smem_u32(&v[(l7 + ((lane >> 3) & 1) * 8) * AROW
                                    + (lane >> 4) * 8]);

    float s[8][4];
#pragma unroll
    for (int nt = 0; nt < 8; nt++)
#pragma unroll
        for (int i = 0; i < 4; i++) s[nt][i] = 0.f;

#pragma unroll
    for (int kt = 0; kt < 2; kt++) {
        uint32_t a0, a1, a2, a3;
        ldsm4(a0, a1, a2, a3, qA + kt * 32);
#pragma unroll
        for (int p = 0; p < 4; p++) {
            uint32_t b0, b1, b2, b3;
            ldsm4(b0, b1, b2, b3, kB + p * 16 * AROW * 2 + kt * 32);
            mma16816(s[2 * p],     a0, a1, a2, a3, b0, b1);
            mma16816(s[2 * p + 1], a0, a1, a2, a3, b2, b3);
        }
    }

    // softmax over cols 0..55 (nt<7); cols 56..63 are pad (exp == 0)
    const int r = lane >> 2, c = lane & 3;
    const __half* bp0 = &bs[(wr + r) * BIASROW + 2 * c];
    const __half* bp1 = &bs[(wr + r + 8) * BIASROW + 2 * c];
#pragma unroll
    for (int nt = 0; nt < 7; nt++) {
        uint32_t u0 = *(const uint32_t*)(bp0 + nt * 8);
        uint32_t u1 = *(const uint32_t*)(bp1 + nt * 8);
        float2 b0 = __half22float2(*(__half2*)&u0);
        float2 b1 = __half22float2(*(__half2*)&u1);
        s[nt][0] = fmaf(s[nt][0], SCALE, b0.x);
        s[nt][1] = fmaf(s[nt][1], SCALE, b0.y);
        s[nt][2] = fmaf(s[nt][2], SCALE, b1.x);
        s[nt][3] = fmaf(s[nt][3], SCALE, b1.y);
    }
    float m0 = -1e30f, m1 = -1e30f;
#pragma unroll
    for (int nt = 0; nt < 7; nt++) {
        m0 = fmaxf(m0, fmaxf(s[nt][0], s[nt][1]));
        m1 = fmaxf(m1, fmaxf(s[nt][2], s[nt][3]));
    }
    m0 = fmaxf(m0, __shfl_xor_sync(0xffffffffu, m0, 1));
    m0 = fmaxf(m0, __shfl_xor_sync(0xffffffffu, m0, 2));
    m1 = fmaxf(m1, __shfl_xor_sync(0xffffffffu, m1, 1));
    m1 = fmaxf(m1, __shfl_xor_sync(0xffffffffu, m1, 2));
    float sum0 = 0.f, sum1 = 0.f;
#pragma unroll
    for (int nt = 0; nt < 7; nt++) {
        s[nt][0] = __expf(s[nt][0] - m0);
        s[nt][1] = __expf(s[nt][1] - m0);
        s[nt][2] = __expf(s[nt][2] - m1);
        s[nt][3] = __expf(s[nt][3] - m1);
        sum0 += s[nt][0] + s[nt][1];
        sum1 += s[nt][2] + s[nt][3];
    }
    sum0 += __shfl_xor_sync(0xffffffffu, sum0, 1);
    sum0 += __shfl_xor_sync(0xffffffffu, sum0, 2);
    sum1 += __shfl_xor_sync(0xffffffffu, sum1, 1);
    sum1 += __shfl_xor_sync(0xffffffffu, sum1, 2);
    const float inv0 = 1.f / sum0, inv1 = 1.f / sum1;

    uint32_t pf[4][4];
#pragma unroll
    for (int kt = 0; kt < 3; kt++) {
        pf[kt][0] = f22h2(s[2 * kt][0],     s[2 * kt][1]);
        pf[kt][1] = f22h2(s[2 * kt][2],     s[2 * kt][3]);
        pf[kt][2] = f22h2(s[2 * kt + 1][0], s[2 * kt + 1][1]);
        pf[kt][3] = f22h2(s[2 * kt + 1][2], s[2 * kt + 1][3]);
    }
    pf[3][0] = f22h2(s[6][0], s[6][1]);   // cols 48..55
    pf[3][1] = f22h2(s[6][2], s[6][3]);
    pf[3][2] = 0u;                        // cols 56..63: pure pad
    pf[3][3] = 0u;

    float o[4][4];
#pragma unroll
    for (int nb = 0; nb < 4; nb++)
#pragma unroll
        for (int i = 0; i < 4; i++) o[nb][i] = 0.f;
#pragma unroll
    for (int kt = 0; kt < 4; kt++) {
#pragma unroll
        for (int p = 0; p < 2; p++) {
            uint32_t b0, b1, b2, b3;
            ldsm4t(b0, b1, b2, b3, vB + kt * 16 * AROW * 2 + p * 32);
            mma16816(o[2 * p],     pf[kt][0], pf[kt][1], pf[kt][2], pf[kt][3], b0, b1);
            mma16816(o[2 * p + 1], pf[kt][0], pf[kt][1], pf[kt][2], pf[kt][3], b2, b3);
        }
    }

    const int row0 = wr + r, row1 = wr + r + 8;
#pragma unroll
    for (int nb = 0; nb < 4; nb++) {
        const int col = head * DH + nb * 8 + 2 * c;
        if (row0 < NTOK)
            *(uint32_t*)&att[((size_t)win * NTOK + row0) * DIM + col] =
                f22h2(o[nb][0] * inv0, o[nb][1] * inv0);
        if (row1 < NTOK)
            *(uint32_t*)&att[((size_t)win * NTOK + row1) * DIM + col] =
                f22h2(o[nb][2] * inv1, o[nb][3] * inv1);
    }
}

// ------------------------------ prep kernel ---------------------------------
__global__ void prep_small_kernel(const float4* __restrict__ wq,
                                  const float4* __restrict__ wo,
                                  const float*  __restrict__ rel_emb,
                                  const int*    __restrict__ rel_idx,
                                  uint2* __restrict__ wq16,
                                  uint2* __restrict__ wo16,
                                  __half* __restrict__ bias16)
{
    const int NWQ = QKV_E * DIM / 4;
    const int NWO = DIM * DIM / 4;
    const int NB  = HEADS * 64 * 64;
    int i = blockIdx.x * 256 + threadIdx.x;
    if (i < NWQ) {
        float4 v = wq[i];
        wq16[i] = make_uint2(f22h2(v.x, v.y), f22h2(v.z, v.w));
    } else if (i < NWQ + NWO) {
        int j = i - NWQ;
        float4 v = wo[j];
        wo16[j] = make_uint2(f22h2(v.x, v.y), f22h2(v.z, v.w));
    } else if (i < NWQ + NWO + NB) {
        int e = i - NWQ - NWO;
        int h = e >> 12, rc = e & 4095, rr = rc >> 6, cc = rc & 63;
        float bv = (rr < NTOK && cc < NTOK)
                 ? rel_emb[rel_idx[rr * NTOK + cc] * HEADS + h] : -60000.f;
        bias16[e] = __float2half(bv);
    }
}

// ----------------------------------------------------------------------------
extern "C" void kernel_launch(void* const* d_in, const int* in_sizes, int n_in,
                              void* d_out, int out_size)
{
    const float* x       = (const float*)d_in[0];
    const float* w_qkv   = (const float*)d_in[1];
    const float* w_out   = (const float*)d_in[2];
    const float* rel_emb = (const float*)d_in[3];
    const int*   rel_idx = (const int*)d_in[4];
    float* out = (float*)d_out;

    __half *wq16, *wo16, *qkv, *att, *bias16;
    cudaGetSymbolAddress((void**)&wq16, g_wq16);
    cudaGetSymbolAddress((void**)&wo16, g_wo16);
    cudaGetSymbolAddress((void**)&qkv,  g_qkv);
    cudaGetSymbolAddress((void**)&att,  g_att);
    cudaGetSymbolAddress((void**)&bias16, g_bias16);

    cudaFuncSetAttribute((void*)gemm_h_kernel<1, 1>,
                         cudaFuncAttributeMaxDynamicSharedMemorySize, GSMEM);
    cudaFuncSetAttribute((void*)gemm_h_kernel<0, 0>,
                         cudaFuncAttributeMaxDynamicSharedMemorySize, GSMEM);

    {
        int tot = QKV_E * DIM / 4 + DIM * DIM / 4 + HEADS * 64 * 64;
        prep_small_kernel<<<(tot + 255) / 256, 256>>>(
            (const float4*)w_qkv, (const float4*)w_out, rel_emb, rel_idx,
            (uint2*)wq16, (uint2*)wo16, bias16);
    }

    // 1) qkv = x @ w_qkv^T   (A fp32->fp16 conversion fused into slab load)
    gemm_h_kernel<1, 1><<<TTOT / 128, 256, GSMEM>>>(x, wq16, qkv, QKV_E);

    // 2) windowed attention
    attn_kernel<<<WINS * HEADS, 128>>>(qkv, bias16, att);

    // 3) out = att @ w_out^T
    gemm_h_kernel<0, 0><<<TTOT / 128, 256, GSMEM>>>(att, wo16, out, DIM);
}